// round 1
// baseline (speedup 1.0000x reference)
#include <cuda_runtime.h>
#include <math.h>

// ---------------- problem constants ----------------
#define DIMN     64
#define L_DIM    2016
#define DD       2017          // L_DIM + NOISE_DIM
#define BB       512
#define N_INTERV 512
#define HID      512
#define SINK_IT  20

// output offsets (floats) in d_out: (P, L, noises, W, samples)
#define POFF 0
#define LOFF 2097152
#define NOFF 4194304
#define WOFF 4227072
#define SOFF 6324224

// ---------------- device scratch ----------------
__device__ float g_flb[BB * DD];          // full_l_batch
__device__ float g_part[2097152];         // GEMM partials / raw logits
__device__ float g_h1[BB * HID];
__device__ float g_h2[BB * HID];
__device__ float g_sink[BB * 4096];       // sinkhorn workspace (in/out)
__device__ float g_Ct[BB * 4096];         // Ct[b][j][k] = C[k][j] = M[c_k][c_j]
__device__ float g_wnoise[BB];

// ---------------- kernel 1: full_l_batch, noises, L ----------------
__global__ void k_prep(const float* __restrict__ Lp, const float* __restrict__ epsL,
                       float* __restrict__ out) {
    int b = blockIdx.x, tid = threadIdx.x;
    __shared__ float flb[DD];
    for (int d = tid; d < DD; d += 256) {
        float mean = Lp[d];
        float raw  = Lp[DD + d];
        float ls   = tanhf(raw * 0.1f) * 10.0f;
        float v    = mean + expf(ls) * epsL[(size_t)b * DD + d];
        flb[d] = v;
        g_flb[(size_t)b * DD + d] = v;
    }
    __syncthreads();
    if (tid == 0) g_wnoise[b] = flb[L_DIM];
    if (tid < DIMN) out[NOFF + b * DIMN + tid] = flb[L_DIM];
    // batched_L: L[b][jr][ic] = flb[off(ic) + jr-ic-1] for ic<jr else 0
    for (int idx = tid; idx < 4096; idx += 256) {
        int jr = idx >> 6, ic = idx & 63;
        float v = 0.0f;
        if (ic < jr) {
            int t = ic * 63 - (ic * (ic - 1)) / 2 + (jr - ic - 1);
            v = flb[t];
        }
        out[LOFF + (size_t)b * 4096 + idx] = v;
    }
}

// ---------------- generic fp32 SGEMM, 64x64 tile, BK=16, split-K partials ----------------
__global__ void sgemm(int which, const float* __restrict__ Bm, int N, int K, int kChunk) {
    const float* __restrict__ A = (which == 0) ? g_flb : (which == 1) ? g_h1 : g_h2;
    int n0 = blockIdx.x * 64, m0 = blockIdx.y * 64, s = blockIdx.z;
    int k0 = s * kChunk;
    int k1 = min(K, k0 + kChunk);
    __shared__ float As[16][64];
    __shared__ float Bs[16][64];
    int tid = threadIdx.x;
    int tx = tid & 15, ty = tid >> 4;
    float acc[4][4];
    #pragma unroll
    for (int i = 0; i < 4; i++)
        #pragma unroll
        for (int j = 0; j < 4; j++) acc[i][j] = 0.0f;

    int ar = tid >> 2, ak = (tid & 3) * 4;
    int bk = tid >> 4, bn = (tid & 15) * 4;

    for (int kb = k0; kb < k1; kb += 16) {
        #pragma unroll
        for (int q = 0; q < 4; q++) {
            int kk = kb + ak + q;
            As[ak + q][ar] = (kk < k1) ? A[(size_t)(m0 + ar) * K + kk] : 0.0f;
        }
        float4 bv = make_float4(0.f, 0.f, 0.f, 0.f);
        if (kb + bk < k1) bv = *(const float4*)&Bm[(size_t)(kb + bk) * N + n0 + bn];
        *(float4*)&Bs[bk][bn] = bv;
        __syncthreads();
        #pragma unroll
        for (int kk = 0; kk < 16; kk++) {
            float a[4], bvv[4];
            *(float4*)a   = *(const float4*)&As[kk][ty * 4];
            *(float4*)bvv = *(const float4*)&Bs[kk][tx * 4];
            #pragma unroll
            for (int i = 0; i < 4; i++)
                #pragma unroll
                for (int j = 0; j < 4; j++) acc[i][j] += a[i] * bvv[j];
        }
        __syncthreads();
    }
    size_t MN = (size_t)512 * N;
    #pragma unroll
    for (int i = 0; i < 4; i++) {
        float4 o = make_float4(acc[i][0], acc[i][1], acc[i][2], acc[i][3]);
        *(float4*)&g_part[s * MN + (size_t)(m0 + ty * 4 + i) * N + n0 + tx * 4] = o;
    }
}

// ---------------- epilogue: sum partials + bias + gelu ----------------
__global__ void k_epi_gelu(int dst, const float* __restrict__ bias, int S) {
    int idx = blockIdx.x * 256 + threadIdx.x;   // MN = 262144
    float x = bias[idx & 511];
    for (int s = 0; s < S; s++) x += g_part[s * 262144 + idx];
    float x3 = x * x * x;
    float t = tanhf(0.7978845608028654f * (x + 0.044715f * x3));
    float v = 0.5f * x * (1.0f + t);
    if (dst == 0) g_h1[idx] = v; else g_h2[idx] = v;
}

// ---------------- epilogue: logits -> tanh clip + gumbel -> /tau ----------------
__global__ void k_epi_sink(const float* __restrict__ b3, const float* __restrict__ gum) {
    int idx = blockIdx.x * 256 + threadIdx.x;   // 2097152 total
    float x = g_part[idx] + b3[idx & 4095];
    x = tanhf(x * 0.1f) * 10.0f;
    float u = gum[idx];
    u = fmaxf(u, 1e-8f);                        // upper clip 1-1e-8 == 1.0f in fp32: no-op
    float g = -logf(-logf(u));
    g_sink[idx] = (x + g) * 5.0f;               // / TAU (0.2)
}

// ---------------- sinkhorn: 20 iters of row/col logsumexp, then exp ----------------
__global__ void k_sinkhorn() {
    int b = blockIdx.x, tid = threadIdx.x, lane = tid & 31, wid = tid >> 5;
    __shared__ float m[64 * 65];
    for (int idx = tid; idx < 4096; idx += 256)
        m[(idx >> 6) * 65 + (idx & 63)] = g_sink[(size_t)b * 4096 + idx];
    __syncthreads();
    for (int it = 0; it < SINK_IT; it++) {
        for (int r = wid; r < 64; r += 8) {
            float v0 = m[r * 65 + lane], v1 = m[r * 65 + 32 + lane];
            float mx = fmaxf(v0, v1);
            #pragma unroll
            for (int off = 16; off; off >>= 1) mx = fmaxf(mx, __shfl_xor_sync(~0u, mx, off));
            float s = expf(v0 - mx) + expf(v1 - mx);
            #pragma unroll
            for (int off = 16; off; off >>= 1) s += __shfl_xor_sync(~0u, s, off);
            float lse = mx + logf(s);
            m[r * 65 + lane] = v0 - lse;
            m[r * 65 + 32 + lane] = v1 - lse;
        }
        __syncthreads();
        for (int c = wid; c < 64; c += 8) {
            float v0 = m[lane * 65 + c], v1 = m[(lane + 32) * 65 + c];
            float mx = fmaxf(v0, v1);
            #pragma unroll
            for (int off = 16; off; off >>= 1) mx = fmaxf(mx, __shfl_xor_sync(~0u, mx, off));
            float s = expf(v0 - mx) + expf(v1 - mx);
            #pragma unroll
            for (int off = 16; off; off >>= 1) s += __shfl_xor_sync(~0u, s, off);
            float lse = mx + logf(s);
            m[lane * 65 + c] = v0 - lse;
            m[(lane + 32) * 65 + c] = v1 - lse;
        }
        __syncthreads();
    }
    for (int idx = tid; idx < 4096; idx += 256)
        g_sink[(size_t)b * 4096 + idx] = expf(m[(idx >> 6) * 65 + (idx & 63)]);
}

// ---------------- greedy perm + P + W + triangular inverse M + Ct ----------------
__global__ void k_greedy(float* __restrict__ out) {
    int b = blockIdx.x, tid = threadIdx.x, lane = tid & 31;
    __shared__ float Lsh[64 * 65];
    __shared__ float SM[64 * 65];   // soft, later reused as M
    __shared__ int colsh[64];
    const float* Lg = out + LOFF + (size_t)b * 4096;
    for (int idx = tid; idx < 4096; idx += 256) {
        int r = idx >> 6, c = idx & 63;
        Lsh[r * 65 + c] = Lg[idx];
        SM[r * 65 + c]  = g_sink[(size_t)b * 4096 + idx];
    }
    __syncthreads();
    if (tid < 32) {
        bool av0 = true, av1 = true;
        for (int i = 0; i < 64; i++) {
            float v0 = av0 ? SM[i * 65 + lane] : -1e30f;
            float v1 = av1 ? SM[i * 65 + 32 + lane] : -1e30f;
            float bv = v0; int bi = lane;
            if (v1 > v0) { bv = v1; bi = lane + 32; }
            #pragma unroll
            for (int off = 16; off; off >>= 1) {
                float ov = __shfl_xor_sync(~0u, bv, off);
                int   oi = __shfl_xor_sync(~0u, bi, off);
                if (ov > bv || (ov == bv && oi < bi)) { bv = ov; bi = oi; }
            }
            if (bi == lane) av0 = false;
            if (bi == lane + 32) av1 = false;
            if (lane == 0) colsh[i] = bi;
        }
    }
    __syncthreads();
    if (tid >= 64) {
        for (int idx = tid - 64; idx < 4096; idx += 192) {
            int i = idx >> 6, l = idx & 63;
            out[POFF + (size_t)b * 4096 + idx] = (l == colsh[i]) ? 1.0f : 0.0f;
            out[WOFF + (size_t)b * 4096 + idx] = Lsh[colsh[i] * 65 + colsh[l]];
        }
    } else {
        // back-substitution: M = (I - L^T)^{-1}, column bc, rows a descending
        int bc = tid;
        for (int a = 63; a >= 0; a--) {
            float acc = (a == bc) ? 1.0f : 0.0f;
            for (int k = a + 1; k <= bc; k++)
                acc += Lsh[k * 65 + a] * SM[k * 65 + bc];
            SM[a * 65 + bc] = acc;
        }
    }
    __syncthreads();
    // Ct[b][j][k] = M[c_k][c_j]
    for (int idx = tid; idx < 4096; idx += 256) {
        int j = idx >> 6, k = idx & 63;
        g_Ct[(size_t)b * 4096 + idx] = SM[colsh[k] * 65 + colsh[j]];
    }
}

// ---------------- samples: s0 = w * Z Ct, Sherman-Morrison intervention ----------------
__global__ void k_samples(const float* __restrict__ z, const int* __restrict__ tg,
                          float* __restrict__ out) {
    extern __shared__ float sh[];
    float* ct  = sh;                 // 64 * 68
    float* zsh = sh + 64 * 68;       // 256 * 65
    int b = blockIdx.x >> 1, i0 = (blockIdx.x & 1) * 256;
    int tid = threadIdx.x;
    for (int idx = tid; idx < 4096; idx += 256)
        ct[(idx >> 6) * 68 + (idx & 63)] = g_Ct[(size_t)b * 4096 + idx];
    for (int idx = tid; idx < 256 * 64; idx += 256)
        zsh[(idx >> 6) * 65 + (idx & 63)] = z[(size_t)(i0 + (idx >> 6)) * 64 + (idx & 63)];
    __syncthreads();

    float acc[64];
    #pragma unroll
    for (int k = 0; k < 64; k++) acc[k] = 0.0f;
    int t = tg[i0 + tid];
    int trow = (t < 64) ? t : 63;
    float acct = 0.0f;
    const float* zr = &zsh[tid * 65];
    for (int j = 0; j < 64; j++) {
        float zj = zr[j];
        const float4* crow = (const float4*)&ct[j * 68];
        acct += ct[j * 68 + trow] * zj;
        #pragma unroll
        for (int q = 0; q < 16; q++) {
            float4 c = crow[q];
            acc[4 * q + 0] += c.x * zj;
            acc[4 * q + 1] += c.y * zj;
            acc[4 * q + 2] += c.z * zj;
            acc[4 * q + 3] += c.w * zj;
        }
    }
    float w = g_wnoise[b];
    float corr = (t < 64) ? (w * acct) : 0.0f;
    float* orow = out + SOFF + ((size_t)b * 512 + i0 + tid) * 64;
    #pragma unroll
    for (int q = 0; q < 16; q++) {
        float4 c = *(const float4*)&ct[trow * 68 + 4 * q];
        float4 o;
        o.x = w * acc[4 * q + 0] - c.x * corr;
        o.y = w * acc[4 * q + 1] - c.y * corr;
        o.z = w * acc[4 * q + 2] - c.z * corr;
        o.w = w * acc[4 * q + 3] - c.w * corr;
        if (t == 4 * q + 0) o.x = 0.0f;
        if (t == 4 * q + 1) o.y = 0.0f;
        if (t == 4 * q + 2) o.z = 0.0f;
        if (t == 4 * q + 3) o.w = 0.0f;
        *(float4*)&orow[4 * q] = o;
    }
}

// ---------------- launch ----------------
extern "C" void kernel_launch(void* const* d_in, const int* in_sizes, int n_in,
                              void* d_out, int out_size) {
    const float* Lp  = (const float*)d_in[0];
    const float* eps = (const float*)d_in[1];
    const float* gum = (const float*)d_in[2];
    const float* z   = (const float*)d_in[3];
    const float* W1  = (const float*)d_in[4];
    const float* b1  = (const float*)d_in[5];
    const float* W2  = (const float*)d_in[6];
    const float* b2  = (const float*)d_in[7];
    const float* W3  = (const float*)d_in[8];
    const float* b3  = (const float*)d_in[9];
    const int*   tg  = (const int*)d_in[10];
    float* out = (float*)d_out;

    cudaFuncSetAttribute(k_samples, cudaFuncAttributeMaxDynamicSharedMemorySize, 84000);

    k_prep<<<512, 256>>>(Lp, eps, out);

    sgemm<<<dim3(8, 8, 4), 256>>>(0, W1, 512, 2017, 505);
    k_epi_gelu<<<1024, 256>>>(0, b1, 4);

    sgemm<<<dim3(8, 8, 4), 256>>>(1, W2, 512, 512, 128);
    k_epi_gelu<<<1024, 256>>>(1, b2, 4);

    sgemm<<<dim3(64, 8, 1), 256>>>(2, W3, 4096, 512, 512);
    k_epi_sink<<<8192, 256>>>(b3, gum);

    k_sinkhorn<<<512, 256>>>();
    k_greedy<<<512, 256>>>(out);
    k_samples<<<1024, 256, 83968>>>(z, tg, out);
}

// round 2
// speedup vs baseline: 1.5310x; 1.5310x over previous
#include <cuda_runtime.h>
#include <math.h>

// ---------------- problem constants ----------------
#define DIMN     64
#define L_DIM    2016
#define DD       2017          // L_DIM + NOISE_DIM
#define BB       512
#define HID      512

// output offsets (floats) in d_out: (P, L, noises, W, samples)
#define POFF 0
#define LOFF 2097152
#define NOFF 4194304
#define WOFF 4227072
#define SOFF 6324224

typedef unsigned long long ull;

__device__ __forceinline__ ull pack2(float x, float y) {
    ull r; asm("mov.b64 %0,{%1,%2};" : "=l"(r) : "f"(x), "f"(y)); return r;
}
__device__ __forceinline__ void unpack2(ull v, float& x, float& y) {
    asm("mov.b64 {%0,%1},%2;" : "=f"(x), "=f"(y) : "l"(v));
}
__device__ __forceinline__ ull ffma2(ull a, ull b, ull c) {
    ull d; asm("fma.rn.f32x2 %0,%1,%2,%3;" : "=l"(d) : "l"(a), "l"(b), "l"(c)); return d;
}

// ---------------- device scratch ----------------
__device__ float g_flb[BB * DD];
__device__ float g_part[16 * 262144];     // split-K partials (also fits 2 x 2097152)
__device__ float g_h1[BB * HID];
__device__ float g_h2[BB * HID];
__device__ float g_sink[BB * 4096];       // LOG matrix after sinkhorn
__device__ float g_Ct[BB * 4096];         // Ct[b][j][k] = M[c_k][c_j]
__device__ float g_wnoise[BB];

// ---------------- kernel 1: full_l_batch, noises, L ----------------
__global__ void k_prep(const float* __restrict__ Lp, const float* __restrict__ epsL,
                       float* __restrict__ out) {
    int b = blockIdx.x, tid = threadIdx.x;
    __shared__ float flb[DD];
    for (int d = tid; d < DD; d += 256) {
        float mean = Lp[d];
        float raw  = Lp[DD + d];
        float ls   = tanhf(raw * 0.1f) * 10.0f;
        float v    = mean + expf(ls) * epsL[(size_t)b * DD + d];
        flb[d] = v;
        g_flb[(size_t)b * DD + d] = v;
    }
    __syncthreads();
    if (tid == 0) g_wnoise[b] = flb[L_DIM];
    if (tid < DIMN) out[NOFF + b * DIMN + tid] = flb[L_DIM];
    for (int idx = tid; idx < 4096; idx += 256) {
        int jr = idx >> 6, ic = idx & 63;
        float v = 0.0f;
        if (ic < jr) {
            int t = ic * 63 - (ic * (ic - 1)) / 2 + (jr - ic - 1);
            v = flb[t];
        }
        out[LOFF + (size_t)b * 4096 + idx] = v;
    }
}

// ---------------- fp32 SGEMM, 128x64 tile, BK=16, split-K, FFMA2 ----------------
__global__ void __launch_bounds__(256) sgemm(int which, const float* __restrict__ Bm,
                                             int N, int K, int kChunk) {
    const float* __restrict__ A = (which == 0) ? g_flb : (which == 1) ? g_h1 : g_h2;
    int n0 = blockIdx.x * 64, m0 = blockIdx.y * 128, s = blockIdx.z;
    int k0 = s * kChunk;
    int k1 = min(K, k0 + kChunk);
    __shared__ __align__(16) float As[16 * 128];
    __shared__ __align__(16) float Bs[16 * 64];
    int tid = threadIdx.x, tx = tid & 15, ty = tid >> 4;
    ull acc2[4][4];
    #pragma unroll
    for (int p = 0; p < 4; p++)
        #pragma unroll
        for (int j = 0; j < 4; j++) acc2[p][j] = 0ull;

    bool k4 = (K & 3) == 0;

    for (int kb = k0; kb < k1; kb += 16) {
        // load A tile (128 rows x 16 k), transposed into As[k][m]
        #pragma unroll
        for (int h = 0; h < 2; h++) {
            int slot = tid + h * 256;
            int row = slot >> 2, kq = slot & 3;
            int kk = kb + kq * 4;
            const float* ap = &A[(size_t)(m0 + row) * K + kk];
            float v0, v1, v2, v3;
            if (k4 && kk + 3 < k1) {
                float4 av = *(const float4*)ap;
                v0 = av.x; v1 = av.y; v2 = av.z; v3 = av.w;
            } else {
                v0 = (kk + 0 < k1) ? ap[0] : 0.0f;
                v1 = (kk + 1 < k1) ? ap[1] : 0.0f;
                v2 = (kk + 2 < k1) ? ap[2] : 0.0f;
                v3 = (kk + 3 < k1) ? ap[3] : 0.0f;
            }
            As[(kq * 4 + 0) * 128 + row] = v0;
            As[(kq * 4 + 1) * 128 + row] = v1;
            As[(kq * 4 + 2) * 128 + row] = v2;
            As[(kq * 4 + 3) * 128 + row] = v3;
        }
        // load B tile (16 k x 64 n)
        {
            int bk = tid >> 4, bn = (tid & 15) * 4;
            float4 bv = make_float4(0.f, 0.f, 0.f, 0.f);
            if (kb + bk < k1) bv = *(const float4*)&Bm[(size_t)(kb + bk) * N + n0 + bn];
            *(float4*)&Bs[bk * 64 + bn] = bv;
        }
        __syncthreads();
        #pragma unroll
        for (int kk = 0; kk < 16; kk++) {
            ulonglong2 aA = *(const ulonglong2*)&As[kk * 128 + ty * 8];
            ulonglong2 aB = *(const ulonglong2*)&As[kk * 128 + ty * 8 + 4];
            float4 b = *(const float4*)&Bs[kk * 64 + tx * 4];
            ull bp0 = pack2(b.x, b.x), bp1 = pack2(b.y, b.y);
            ull bp2 = pack2(b.z, b.z), bp3 = pack2(b.w, b.w);
            acc2[0][0] = ffma2(aA.x, bp0, acc2[0][0]);
            acc2[0][1] = ffma2(aA.x, bp1, acc2[0][1]);
            acc2[0][2] = ffma2(aA.x, bp2, acc2[0][2]);
            acc2[0][3] = ffma2(aA.x, bp3, acc2[0][3]);
            acc2[1][0] = ffma2(aA.y, bp0, acc2[1][0]);
            acc2[1][1] = ffma2(aA.y, bp1, acc2[1][1]);
            acc2[1][2] = ffma2(aA.y, bp2, acc2[1][2]);
            acc2[1][3] = ffma2(aA.y, bp3, acc2[1][3]);
            acc2[2][0] = ffma2(aB.x, bp0, acc2[2][0]);
            acc2[2][1] = ffma2(aB.x, bp1, acc2[2][1]);
            acc2[2][2] = ffma2(aB.x, bp2, acc2[2][2]);
            acc2[2][3] = ffma2(aB.x, bp3, acc2[2][3]);
            acc2[3][0] = ffma2(aB.y, bp0, acc2[3][0]);
            acc2[3][1] = ffma2(aB.y, bp1, acc2[3][1]);
            acc2[3][2] = ffma2(aB.y, bp2, acc2[3][2]);
            acc2[3][3] = ffma2(aB.y, bp3, acc2[3][3]);
        }
        __syncthreads();
    }
    size_t MN = (size_t)512 * N;
    float* dst = &g_part[(size_t)s * MN];
    #pragma unroll
    for (int p = 0; p < 4; p++) {
        float lo[4], hi[4];
        #pragma unroll
        for (int j = 0; j < 4; j++) unpack2(acc2[p][j], lo[j], hi[j]);
        int m = m0 + ty * 8 + 2 * p;
        *(float4*)&dst[(size_t)m * N + n0 + tx * 4] = make_float4(lo[0], lo[1], lo[2], lo[3]);
        *(float4*)&dst[(size_t)(m + 1) * N + n0 + tx * 4] = make_float4(hi[0], hi[1], hi[2], hi[3]);
    }
}

// ---------------- epilogue: sum partials + bias + gelu ----------------
__global__ void k_epi_gelu(int dst, const float* __restrict__ bias, int S) {
    int idx = blockIdx.x * 256 + threadIdx.x;   // MN = 262144
    float x = bias[idx & 511];
    for (int s = 0; s < S; s++) x += g_part[s * 262144 + idx];
    float x3 = x * x * x;
    float t = tanhf(0.7978845608028654f * (x + 0.044715f * x3));
    float v = 0.5f * x * (1.0f + t);
    if (dst == 0) g_h1[idx] = v; else g_h2[idx] = v;
}

// ---------------- epilogue: logits -> tanh clip + gumbel -> /tau (log space) ----------------
__global__ void k_epi_sink(const float* __restrict__ b3, const float* __restrict__ gum) {
    int idx = blockIdx.x * 256 + threadIdx.x;   // 2097152 total
    float x = g_part[idx] + g_part[2097152 + idx] + b3[idx & 4095];
    x = tanhf(x * 0.1f) * 10.0f;
    float u = gum[idx];
    u = fmaxf(u, 1e-8f);
    float g = -logf(-logf(u));
    g_sink[idx] = (x + g) * 5.0f;               // / TAU (0.2)
}

// ---------------- sinkhorn: 20 iters, ILP-interleaved, log-space output ----------------
__global__ void __launch_bounds__(256) k_sinkhorn() {
    int b = blockIdx.x, tid = threadIdx.x, lane = tid & 31, wd = tid >> 5;
    __shared__ float m[64 * 65];
    for (int idx = tid; idx < 4096; idx += 256)
        m[(idx >> 6) * 65 + (idx & 63)] = g_sink[(size_t)b * 4096 + idx];
    __syncthreads();
    int r0 = wd * 8;
    float a[8], c[8], sm[8];
    for (int it = 0; it < 20; it++) {
        // row pass
        #pragma unroll
        for (int q = 0; q < 8; q++) {
            a[q] = m[(r0 + q) * 65 + lane];
            c[q] = m[(r0 + q) * 65 + 32 + lane];
        }
        if (it == 0) {
            float mx[8];
            #pragma unroll
            for (int q = 0; q < 8; q++) mx[q] = fmaxf(a[q], c[q]);
            #pragma unroll
            for (int off = 16; off; off >>= 1)
                #pragma unroll
                for (int q = 0; q < 8; q++) mx[q] = fmaxf(mx[q], __shfl_xor_sync(~0u, mx[q], off));
            #pragma unroll
            for (int q = 0; q < 8; q++) sm[q] = __expf(a[q] - mx[q]) + __expf(c[q] - mx[q]);
            #pragma unroll
            for (int off = 16; off; off >>= 1)
                #pragma unroll
                for (int q = 0; q < 8; q++) sm[q] += __shfl_xor_sync(~0u, sm[q], off);
            #pragma unroll
            for (int q = 0; q < 8; q++) {
                float lse = mx[q] + __logf(sm[q]);
                a[q] -= lse; c[q] -= lse;
            }
        } else {
            #pragma unroll
            for (int q = 0; q < 8; q++) sm[q] = __expf(a[q]) + __expf(c[q]);
            #pragma unroll
            for (int off = 16; off; off >>= 1)
                #pragma unroll
                for (int q = 0; q < 8; q++) sm[q] += __shfl_xor_sync(~0u, sm[q], off);
            #pragma unroll
            for (int q = 0; q < 8; q++) {
                float lse = __logf(sm[q]);
                a[q] -= lse; c[q] -= lse;
            }
        }
        #pragma unroll
        for (int q = 0; q < 8; q++) {
            m[(r0 + q) * 65 + lane] = a[q];
            m[(r0 + q) * 65 + 32 + lane] = c[q];
        }
        __syncthreads();
        // col pass (entries <= 0 after row pass: no max needed)
        #pragma unroll
        for (int q = 0; q < 8; q++) {
            a[q] = m[lane * 65 + r0 + q];
            c[q] = m[(lane + 32) * 65 + r0 + q];
        }
        #pragma unroll
        for (int q = 0; q < 8; q++) sm[q] = __expf(a[q]) + __expf(c[q]);
        #pragma unroll
        for (int off = 16; off; off >>= 1)
            #pragma unroll
            for (int q = 0; q < 8; q++) sm[q] += __shfl_xor_sync(~0u, sm[q], off);
        #pragma unroll
        for (int q = 0; q < 8; q++) {
            float lse = __logf(sm[q]);
            m[lane * 65 + r0 + q] = a[q] - lse;
            m[(lane + 32) * 65 + r0 + q] = c[q] - lse;
        }
        __syncthreads();
    }
    // store LOG matrix (argmax downstream is monotone-invariant)
    for (int idx = tid; idx < 4096; idx += 256)
        g_sink[(size_t)b * 4096 + idx] = m[(idx >> 6) * 65 + (idx & 63)];
}

// ---------------- greedy perm + P + W + triangular inverse M + Ct ----------------
__global__ void __launch_bounds__(256) k_greedy(float* __restrict__ out) {
    extern __shared__ float dsm[];
    float* Lsh = dsm;              // 64*65
    float* Ssh = dsm + 64 * 65;    // log-soft
    float* Msh = dsm + 2 * 64 * 65;
    __shared__ int colsh[64];
    int b = blockIdx.x, tid = threadIdx.x;
    const float* Lg = out + LOFF + (size_t)b * 4096;
    for (int idx = tid; idx < 4096; idx += 256) {
        int r = idx >> 6, cc = idx & 63;
        Lsh[r * 65 + cc] = Lg[idx];
        Ssh[r * 65 + cc] = g_sink[(size_t)b * 4096 + idx];
    }
    __syncthreads();
    if (tid >= 224) {
        // greedy argmax on log-soft (warp 7), concurrent with back-substitution
        int lane = tid & 31;
        bool av0 = true, av1 = true;
        for (int i = 0; i < 64; i++) {
            float v0 = av0 ? Ssh[i * 65 + lane] : -1e30f;
            float v1 = av1 ? Ssh[i * 65 + 32 + lane] : -1e30f;
            float bv = v0; int bi = lane;
            if (v1 > v0) { bv = v1; bi = lane + 32; }
            #pragma unroll
            for (int off = 16; off; off >>= 1) {
                float ov = __shfl_xor_sync(~0u, bv, off);
                int   oi = __shfl_xor_sync(~0u, bi, off);
                if (ov > bv || (ov == bv && oi < bi)) { bv = ov; bi = oi; }
            }
            if (bi == lane) av0 = false;
            if (bi == lane + 32) av1 = false;
            if (lane == 0) colsh[i] = bi;
        }
    } else if (tid < 64) {
        // back-substitution: M = (I - L^T)^{-1}
        int bc = tid;
        for (int a = 63; a >= 0; a--) {
            float acc0 = (a == bc) ? 1.0f : 0.0f, acc1 = 0.0f;
            int k = a + 1;
            for (; k + 1 <= bc; k += 2) {
                acc0 += Lsh[k * 65 + a] * Msh[k * 65 + bc];
                acc1 += Lsh[(k + 1) * 65 + a] * Msh[(k + 1) * 65 + bc];
            }
            if (k <= bc) acc0 += Lsh[k * 65 + a] * Msh[k * 65 + bc];
            Msh[a * 65 + bc] = acc0 + acc1;
        }
    }
    __syncthreads();
    for (int idx = tid; idx < 4096; idx += 256) {
        int i = idx >> 6, l = idx & 63;
        out[POFF + (size_t)b * 4096 + idx] = (l == colsh[i]) ? 1.0f : 0.0f;
        out[WOFF + (size_t)b * 4096 + idx] = Lsh[colsh[i] * 65 + colsh[l]];
        g_Ct[(size_t)b * 4096 + idx] = Msh[colsh[l] * 65 + colsh[i]];
    }
}

// ---------------- samples: tiled GEMM (128x64, K=64) + Sherman-Morrison ----------------
__global__ void __launch_bounds__(256) k_samples(const float* __restrict__ z,
                                                 const int* __restrict__ tg,
                                                 float* __restrict__ out) {
    extern __shared__ float sh[];
    float* Zs = sh;            // [64][128] transposed Z tile; reused as S0s[128][64]
    float* Cs = sh + 8192;     // [64][68] Ct
    __shared__ int tgs[128];
    __shared__ float wsh;
    int blk = blockIdx.x, b = blk >> 2, i0 = (blk & 3) * 128;
    int tid = threadIdx.x, tx = tid & 15, ty = tid >> 4;

    #pragma unroll
    for (int h = 0; h < 8; h++) {
        int slot = tid + h * 256;            // 2048 slots: 128 rows x 16 k-quads
        int row = slot >> 4, kq = slot & 15;
        float4 zv = *(const float4*)&z[(size_t)(i0 + row) * 64 + kq * 4];
        Zs[(kq * 4 + 0) * 128 + row] = zv.x;
        Zs[(kq * 4 + 1) * 128 + row] = zv.y;
        Zs[(kq * 4 + 2) * 128 + row] = zv.z;
        Zs[(kq * 4 + 3) * 128 + row] = zv.w;
    }
    #pragma unroll
    for (int h = 0; h < 4; h++) {
        int slot = tid + h * 256;            // 1024 slots: 64 rows x 16 k-quads
        int j = slot >> 4, kq = slot & 15;
        float4 cv = *(const float4*)&g_Ct[(size_t)b * 4096 + j * 64 + kq * 4];
        *(float4*)&Cs[j * 68 + kq * 4] = cv;
    }
    if (tid < 128) tgs[tid] = tg[i0 + tid];
    if (tid == 0) wsh = g_wnoise[b];
    __syncthreads();

    ull acc2[4][4];
    #pragma unroll
    for (int p = 0; p < 4; p++)
        #pragma unroll
        for (int j = 0; j < 4; j++) acc2[p][j] = 0ull;

    #pragma unroll 8
    for (int j = 0; j < 64; j++) {
        ulonglong2 aA = *(const ulonglong2*)&Zs[j * 128 + ty * 8];
        ulonglong2 aB = *(const ulonglong2*)&Zs[j * 128 + ty * 8 + 4];
        float4 bv = *(const float4*)&Cs[j * 68 + tx * 4];
        ull bp0 = pack2(bv.x, bv.x), bp1 = pack2(bv.y, bv.y);
        ull bp2 = pack2(bv.z, bv.z), bp3 = pack2(bv.w, bv.w);
        acc2[0][0] = ffma2(aA.x, bp0, acc2[0][0]);
        acc2[0][1] = ffma2(aA.x, bp1, acc2[0][1]);
        acc2[0][2] = ffma2(aA.x, bp2, acc2[0][2]);
        acc2[0][3] = ffma2(aA.x, bp3, acc2[0][3]);
        acc2[1][0] = ffma2(aA.y, bp0, acc2[1][0]);
        acc2[1][1] = ffma2(aA.y, bp1, acc2[1][1]);
        acc2[1][2] = ffma2(aA.y, bp2, acc2[1][2]);
        acc2[1][3] = ffma2(aA.y, bp3, acc2[1][3]);
        acc2[2][0] = ffma2(aB.x, bp0, acc2[2][0]);
        acc2[2][1] = ffma2(aB.x, bp1, acc2[2][1]);
        acc2[2][2] = ffma2(aB.x, bp2, acc2[2][2]);
        acc2[2][3] = ffma2(aB.x, bp3, acc2[2][3]);
        acc2[3][0] = ffma2(aB.y, bp0, acc2[3][0]);
        acc2[3][1] = ffma2(aB.y, bp1, acc2[3][1]);
        acc2[3][2] = ffma2(aB.y, bp2, acc2[3][2]);
        acc2[3][3] = ffma2(aB.y, bp3, acc2[3][3]);
    }
    __syncthreads();   // all reads of Zs done before reuse as S0s
    #pragma unroll
    for (int p = 0; p < 4; p++)
        #pragma unroll
        for (int j = 0; j < 4; j++) {
            float lo, hi;
            unpack2(acc2[p][j], lo, hi);
            Zs[(ty * 8 + 2 * p) * 64 + tx * 4 + j] = lo;
            Zs[(ty * 8 + 2 * p + 1) * 64 + tx * 4 + j] = hi;
        }
    __syncthreads();
    float w = wsh;
    #pragma unroll
    for (int rr = 0; rr < 8; rr++) {
        int m = ty * 8 + rr;
        int t = tgs[m];
        int trow = (t < 64) ? t : 63;
        float corr = (t < 64) ? (w * Zs[m * 64 + trow]) : 0.0f;
        float4 s0v = *(const float4*)&Zs[m * 64 + tx * 4];
        float4 cv  = *(const float4*)&Cs[trow * 68 + tx * 4];
        float4 o;
        o.x = w * s0v.x - cv.x * corr;
        o.y = w * s0v.y - cv.y * corr;
        o.z = w * s0v.z - cv.z * corr;
        o.w = w * s0v.w - cv.w * corr;
        int n0 = tx * 4;
        if (t == n0 + 0) o.x = 0.0f;
        if (t == n0 + 1) o.y = 0.0f;
        if (t == n0 + 2) o.z = 0.0f;
        if (t == n0 + 3) o.w = 0.0f;
        *(float4*)&out[SOFF + ((size_t)b * 512 + i0 + m) * 64 + n0] = o;
    }
}

// ---------------- launch ----------------
extern "C" void kernel_launch(void* const* d_in, const int* in_sizes, int n_in,
                              void* d_out, int out_size) {
    const float* Lp  = (const float*)d_in[0];
    const float* eps = (const float*)d_in[1];
    const float* gum = (const float*)d_in[2];
    const float* z   = (const float*)d_in[3];
    const float* W1  = (const float*)d_in[4];
    const float* b1  = (const float*)d_in[5];
    const float* W2  = (const float*)d_in[6];
    const float* b2  = (const float*)d_in[7];
    const float* W3  = (const float*)d_in[8];
    const float* b3  = (const float*)d_in[9];
    const int*   tg  = (const int*)d_in[10];
    float* out = (float*)d_out;

    cudaFuncSetAttribute(k_greedy, cudaFuncAttributeMaxDynamicSharedMemorySize, 50176);
    cudaFuncSetAttribute(k_samples, cudaFuncAttributeMaxDynamicSharedMemorySize, 50176);

    k_prep<<<512, 256>>>(Lp, eps, out);

    sgemm<<<dim3(8, 4, 16), 256>>>(0, W1, 512, 2017, 128);
    k_epi_gelu<<<1024, 256>>>(0, b1, 16);

    sgemm<<<dim3(8, 4, 16), 256>>>(1, W2, 512, 512, 32);
    k_epi_gelu<<<1024, 256>>>(1, b2, 16);

    sgemm<<<dim3(64, 4, 2), 256>>>(2, W3, 4096, 512, 256);
    k_epi_sink<<<8192, 256>>>(b3, gum);

    k_sinkhorn<<<512, 256>>>();
    k_greedy<<<512, 256, 49920>>>(out);
    k_samples<<<2048, 256, 50176>>>(z, tg, out);
}

// round 3
// speedup vs baseline: 1.5470x; 1.0104x over previous
#include <cuda_runtime.h>
#include <math.h>

// ---------------- problem constants ----------------
#define DIMN     64
#define L_DIM    2016
#define DD       2017          // L_DIM + NOISE_DIM
#define BB       512
#define HID      512

// output offsets (floats) in d_out: (P, L, noises, W, samples)
#define POFF 0
#define LOFF 2097152
#define NOFF 4194304
#define WOFF 4227072
#define SOFF 6324224

typedef unsigned long long ull;

__device__ __forceinline__ ull pack2(float x, float y) {
    ull r; asm("mov.b64 %0,{%1,%2};" : "=l"(r) : "f"(x), "f"(y)); return r;
}
__device__ __forceinline__ void unpack2(ull v, float& x, float& y) {
    asm("mov.b64 {%0,%1},%2;" : "=f"(x), "=f"(y) : "l"(v));
}
__device__ __forceinline__ ull ffma2(ull a, ull b, ull c) {
    ull d; asm("fma.rn.f32x2 %0,%1,%2,%3;" : "=l"(d) : "l"(a), "l"(b), "l"(c)); return d;
}

// ---------------- device scratch ----------------
__device__ float g_flb[BB * DD];
__device__ float g_part[16 * 262144];     // split-K partials (fits 2 x 2097152 for logits)
__device__ float g_h1[BB * HID];
__device__ float g_h2[BB * HID];
__device__ float g_Ct[BB * 4096];         // Ct[b][j][k] = M[c_k][c_j]
__device__ float g_wnoise[BB];

// ---------------- kernel 1: full_l_batch, noises, L ----------------
__global__ void k_prep(const float* __restrict__ Lp, const float* __restrict__ epsL,
                       float* __restrict__ out) {
    int b = blockIdx.x, tid = threadIdx.x;
    __shared__ float flb[DD];
    for (int d = tid; d < DD; d += 256) {
        float mean = Lp[d];
        float raw  = Lp[DD + d];
        float ls   = tanhf(raw * 0.1f) * 10.0f;
        float v    = mean + expf(ls) * epsL[(size_t)b * DD + d];
        flb[d] = v;
        g_flb[(size_t)b * DD + d] = v;
    }
    __syncthreads();
    if (tid == 0) g_wnoise[b] = flb[L_DIM];
    if (tid < DIMN) out[NOFF + b * DIMN + tid] = flb[L_DIM];
    for (int idx = tid; idx < 4096; idx += 256) {
        int jr = idx >> 6, ic = idx & 63;
        float v = 0.0f;
        if (ic < jr) {
            int t = ic * 63 - (ic * (ic - 1)) / 2 + (jr - ic - 1);
            v = flb[t];
        }
        out[LOFF + (size_t)b * 4096 + idx] = v;
    }
}

// ---------------- fp32 SGEMM, 128x64 tile, BK=16, split-K, FFMA2, prefetch ----------------
__global__ void __launch_bounds__(256) sgemm(int which, const float* __restrict__ Bm,
                                             int N, int K, int kChunk) {
    const float* __restrict__ A = (which == 0) ? g_flb : (which == 1) ? g_h1 : g_h2;
    int n0 = blockIdx.x * 64, m0 = blockIdx.y * 128, s = blockIdx.z;
    int k0 = s * kChunk;
    int k1 = min(K, k0 + kChunk);
    __shared__ __align__(16) float As[16 * 128];
    __shared__ __align__(16) float Bs[16 * 64];
    int tid = threadIdx.x, tx = tid & 15, ty = tid >> 4;
    ull acc2[4][4];
    #pragma unroll
    for (int p = 0; p < 4; p++)
        #pragma unroll
        for (int j = 0; j < 4; j++) acc2[p][j] = 0ull;

    bool k4 = (K & 3) == 0;
    int ar0 = tid >> 2, ak = (tid & 3) * 4;   // A: rows ar0 and ar0+64, k offset ak
    int bk = tid >> 4, bn = (tid & 15) * 4;   // B: 1 float4

    float pa0[4], pa1[4];
    float4 pb;

    auto fetch = [&](int kb) {
        int kk = kb + ak;
        const float* ap0 = &A[(size_t)(m0 + ar0) * K + kk];
        const float* ap1 = &A[(size_t)(m0 + ar0 + 64) * K + kk];
        if (k4) {
            float4 v0 = *(const float4*)ap0;
            float4 v1 = *(const float4*)ap1;
            pa0[0] = v0.x; pa0[1] = v0.y; pa0[2] = v0.z; pa0[3] = v0.w;
            pa1[0] = v1.x; pa1[1] = v1.y; pa1[2] = v1.z; pa1[3] = v1.w;
        } else {
            #pragma unroll
            for (int q = 0; q < 4; q++) {
                pa0[q] = (kk + q < k1) ? ap0[q] : 0.0f;
                pa1[q] = (kk + q < k1) ? ap1[q] : 0.0f;
            }
        }
        pb = make_float4(0.f, 0.f, 0.f, 0.f);
        if (kb + bk < k1) pb = *(const float4*)&Bm[(size_t)(kb + bk) * N + n0 + bn];
    };

    fetch(k0);
    for (int kb = k0; kb < k1; kb += 16) {
        #pragma unroll
        for (int q = 0; q < 4; q++) {
            As[(ak + q) * 128 + ar0] = pa0[q];
            As[(ak + q) * 128 + ar0 + 64] = pa1[q];
        }
        *(float4*)&Bs[bk * 64 + bn] = pb;
        __syncthreads();
        if (kb + 16 < k1) fetch(kb + 16);
        #pragma unroll
        for (int kk = 0; kk < 16; kk++) {
            ulonglong2 aA = *(const ulonglong2*)&As[kk * 128 + ty * 8];
            ulonglong2 aB = *(const ulonglong2*)&As[kk * 128 + ty * 8 + 4];
            float4 b = *(const float4*)&Bs[kk * 64 + tx * 4];
            ull bp0 = pack2(b.x, b.x), bp1 = pack2(b.y, b.y);
            ull bp2 = pack2(b.z, b.z), bp3 = pack2(b.w, b.w);
            acc2[0][0] = ffma2(aA.x, bp0, acc2[0][0]);
            acc2[0][1] = ffma2(aA.x, bp1, acc2[0][1]);
            acc2[0][2] = ffma2(aA.x, bp2, acc2[0][2]);
            acc2[0][3] = ffma2(aA.x, bp3, acc2[0][3]);
            acc2[1][0] = ffma2(aA.y, bp0, acc2[1][0]);
            acc2[1][1] = ffma2(aA.y, bp1, acc2[1][1]);
            acc2[1][2] = ffma2(aA.y, bp2, acc2[1][2]);
            acc2[1][3] = ffma2(aA.y, bp3, acc2[1][3]);
            acc2[2][0] = ffma2(aB.x, bp0, acc2[2][0]);
            acc2[2][1] = ffma2(aB.x, bp1, acc2[2][1]);
            acc2[2][2] = ffma2(aB.x, bp2, acc2[2][2]);
            acc2[2][3] = ffma2(aB.x, bp3, acc2[2][3]);
            acc2[3][0] = ffma2(aB.y, bp0, acc2[3][0]);
            acc2[3][1] = ffma2(aB.y, bp1, acc2[3][1]);
            acc2[3][2] = ffma2(aB.y, bp2, acc2[3][2]);
            acc2[3][3] = ffma2(aB.y, bp3, acc2[3][3]);
        }
        __syncthreads();
    }
    size_t MN = (size_t)512 * N;
    float* dst = &g_part[(size_t)s * MN];
    #pragma unroll
    for (int p = 0; p < 4; p++) {
        float lo[4], hi[4];
        #pragma unroll
        for (int j = 0; j < 4; j++) unpack2(acc2[p][j], lo[j], hi[j]);
        int m = m0 + ty * 8 + 2 * p;
        *(float4*)&dst[(size_t)m * N + n0 + tx * 4] = make_float4(lo[0], lo[1], lo[2], lo[3]);
        *(float4*)&dst[(size_t)(m + 1) * N + n0 + tx * 4] = make_float4(hi[0], hi[1], hi[2], hi[3]);
    }
}

// ---------------- epilogue: sum 16 partials + bias + gelu ----------------
__global__ void k_epi_gelu(int dst, const float* __restrict__ bias) {
    int idx = blockIdx.x * 256 + threadIdx.x;   // MN = 262144
    float x = bias[idx & 511];
    #pragma unroll
    for (int s = 0; s < 16; s++) x += g_part[s * 262144 + idx];
    float x3 = x * x * x;
    float t = tanhf(0.7978845608028654f * (x + 0.044715f * x3));
    float v = 0.5f * x * (1.0f + t);
    if (dst == 0) g_h1[idx] = v; else g_h2[idx] = v;
}

// ---- fused: logits epilogue + gumbel + 20x sinkhorn + greedy + backsub + P/W/Ct ----
__global__ void __launch_bounds__(256) k_sinkgreedy(const float* __restrict__ b3,
                                                    const float* __restrict__ gum,
                                                    float* __restrict__ out) {
    extern __shared__ float dsm[];
    float* m   = dsm;               // 64*65 log matrix
    float* Lsh = dsm + 64 * 65;
    float* Msh = dsm + 2 * 64 * 65;
    __shared__ int colsh[64];
    int b = blockIdx.x, tid = threadIdx.x, lane = tid & 31, wd = tid >> 5;

    // logits epilogue: partial-sum + bias + tanh clip + gumbel, into log space /tau
    const float* Lg = out + LOFF + (size_t)b * 4096;
    for (int idx = tid; idx < 4096; idx += 256) {
        float x = g_part[(size_t)b * 4096 + idx] + g_part[2097152 + (size_t)b * 4096 + idx]
                + b3[idx];
        x = tanhf(x * 0.1f) * 10.0f;
        float u = gum[(size_t)b * 4096 + idx];
        u = fmaxf(u, 1e-8f);
        float g = -logf(-logf(u));
        m[(idx >> 6) * 65 + (idx & 63)] = (x + g) * 5.0f;   // / TAU
        Lsh[(idx >> 6) * 65 + (idx & 63)] = Lg[idx];
    }
    __syncthreads();

    int r0 = wd * 8;
    float a[8], c[8], sm[8];
    for (int it = 0; it < 20; it++) {
        // row pass
        #pragma unroll
        for (int q = 0; q < 8; q++) {
            a[q] = m[(r0 + q) * 65 + lane];
            c[q] = m[(r0 + q) * 65 + 32 + lane];
        }
        if (it == 0) {
            float mx[8];
            #pragma unroll
            for (int q = 0; q < 8; q++) mx[q] = fmaxf(a[q], c[q]);
            #pragma unroll
            for (int off = 16; off; off >>= 1)
                #pragma unroll
                for (int q = 0; q < 8; q++) mx[q] = fmaxf(mx[q], __shfl_xor_sync(~0u, mx[q], off));
            #pragma unroll
            for (int q = 0; q < 8; q++) sm[q] = __expf(a[q] - mx[q]) + __expf(c[q] - mx[q]);
            #pragma unroll
            for (int off = 16; off; off >>= 1)
                #pragma unroll
                for (int q = 0; q < 8; q++) sm[q] += __shfl_xor_sync(~0u, sm[q], off);
            #pragma unroll
            for (int q = 0; q < 8; q++) {
                float lse = mx[q] + __logf(sm[q]);
                a[q] -= lse; c[q] -= lse;
            }
        } else {
            #pragma unroll
            for (int q = 0; q < 8; q++) sm[q] = __expf(a[q]) + __expf(c[q]);
            #pragma unroll
            for (int off = 16; off; off >>= 1)
                #pragma unroll
                for (int q = 0; q < 8; q++) sm[q] += __shfl_xor_sync(~0u, sm[q], off);
            #pragma unroll
            for (int q = 0; q < 8; q++) {
                float lse = __logf(sm[q]);
                a[q] -= lse; c[q] -= lse;
            }
        }
        #pragma unroll
        for (int q = 0; q < 8; q++) {
            m[(r0 + q) * 65 + lane] = a[q];
            m[(r0 + q) * 65 + 32 + lane] = c[q];
        }
        __syncthreads();
        // col pass (entries <= 0 after row pass: no max shift needed)
        #pragma unroll
        for (int q = 0; q < 8; q++) {
            a[q] = m[lane * 65 + r0 + q];
            c[q] = m[(lane + 32) * 65 + r0 + q];
        }
        #pragma unroll
        for (int q = 0; q < 8; q++) sm[q] = __expf(a[q]) + __expf(c[q]);
        #pragma unroll
        for (int off = 16; off; off >>= 1)
            #pragma unroll
            for (int q = 0; q < 8; q++) sm[q] += __shfl_xor_sync(~0u, sm[q], off);
        #pragma unroll
        for (int q = 0; q < 8; q++) {
            float lse = __logf(sm[q]);
            m[lane * 65 + r0 + q] = a[q] - lse;
            m[(lane + 32) * 65 + r0 + q] = c[q] - lse;
        }
        __syncthreads();
    }

    // greedy argmax (warp 7, on log matrix) concurrent with back-substitution (tid<64)
    if (tid >= 224) {
        bool av0 = true, av1 = true;
        for (int i = 0; i < 64; i++) {
            float v0 = av0 ? m[i * 65 + lane] : -1e30f;
            float v1 = av1 ? m[i * 65 + 32 + lane] : -1e30f;
            float bv = v0; int bi = lane;
            if (v1 > v0) { bv = v1; bi = lane + 32; }
            #pragma unroll
            for (int off = 16; off; off >>= 1) {
                float ov = __shfl_xor_sync(~0u, bv, off);
                int   oi = __shfl_xor_sync(~0u, bi, off);
                if (ov > bv || (ov == bv && oi < bi)) { bv = ov; bi = oi; }
            }
            if (bi == lane) av0 = false;
            if (bi == lane + 32) av1 = false;
            if (lane == 0) colsh[i] = bi;
        }
    } else if (tid < 64) {
        // back-substitution: M = (I - L^T)^{-1}
        int bc = tid;
        for (int aa = 63; aa >= 0; aa--) {
            float acc0 = (aa == bc) ? 1.0f : 0.0f, acc1 = 0.0f;
            int k = aa + 1;
            for (; k + 1 <= bc; k += 2) {
                acc0 += Lsh[k * 65 + aa] * Msh[k * 65 + bc];
                acc1 += Lsh[(k + 1) * 65 + aa] * Msh[(k + 1) * 65 + bc];
            }
            if (k <= bc) acc0 += Lsh[k * 65 + aa] * Msh[k * 65 + bc];
            Msh[aa * 65 + bc] = acc0 + acc1;
        }
    }
    __syncthreads();
    for (int idx = tid; idx < 4096; idx += 256) {
        int i = idx >> 6, l = idx & 63;
        out[POFF + (size_t)b * 4096 + idx] = (l == colsh[i]) ? 1.0f : 0.0f;
        out[WOFF + (size_t)b * 4096 + idx] = Lsh[colsh[i] * 65 + colsh[l]];
        g_Ct[(size_t)b * 4096 + idx] = Msh[colsh[l] * 65 + colsh[i]];
    }
}

// ---------------- samples: tiled GEMM (128x64, K=64) + Sherman-Morrison ----------------
__global__ void __launch_bounds__(256) k_samples(const float* __restrict__ z,
                                                 const int* __restrict__ tg,
                                                 float* __restrict__ out) {
    extern __shared__ float sh[];
    float* Zs = sh;            // [64][128] transposed Z tile; reused as S0s[128][64]
    float* Cs = sh + 8192;     // [64][68] Ct
    __shared__ int tgs[128];
    __shared__ float wsh;
    int blk = blockIdx.x, b = blk >> 2, i0 = (blk & 3) * 128;
    int tid = threadIdx.x, tx = tid & 15, ty = tid >> 4;

    #pragma unroll
    for (int h = 0; h < 8; h++) {
        int slot = tid + h * 256;            // 2048 slots: 128 rows x 16 k-quads
        int row = slot >> 4, kq = slot & 15;
        float4 zv = *(const float4*)&z[(size_t)(i0 + row) * 64 + kq * 4];
        Zs[(kq * 4 + 0) * 128 + row] = zv.x;
        Zs[(kq * 4 + 1) * 128 + row] = zv.y;
        Zs[(kq * 4 + 2) * 128 + row] = zv.z;
        Zs[(kq * 4 + 3) * 128 + row] = zv.w;
    }
    #pragma unroll
    for (int h = 0; h < 4; h++) {
        int slot = tid + h * 256;            // 1024 slots: 64 rows x 16 k-quads
        int j = slot >> 4, kq = slot & 15;
        float4 cv = *(const float4*)&g_Ct[(size_t)b * 4096 + j * 64 + kq * 4];
        *(float4*)&Cs[j * 68 + kq * 4] = cv;
    }
    if (tid < 128) tgs[tid] = tg[i0 + tid];
    if (tid == 0) wsh = g_wnoise[b];
    __syncthreads();

    ull acc2[4][4];
    #pragma unroll
    for (int p = 0; p < 4; p++)
        #pragma unroll
        for (int j = 0; j < 4; j++) acc2[p][j] = 0ull;

    const float* zA = &Zs[ty * 8];
    const float* cB = &Cs[tx * 4];
    #pragma unroll 2
    for (int j = 0; j < 64; j++) {
        ulonglong2 aA = *(const ulonglong2*)(zA + j * 128);
        ulonglong2 aB = *(const ulonglong2*)(zA + j * 128 + 4);
        float4 bv = *(const float4*)(cB + j * 68);
        ull bp0 = pack2(bv.x, bv.x), bp1 = pack2(bv.y, bv.y);
        ull bp2 = pack2(bv.z, bv.z), bp3 = pack2(bv.w, bv.w);
        acc2[0][0] = ffma2(aA.x, bp0, acc2[0][0]);
        acc2[0][1] = ffma2(aA.x, bp1, acc2[0][1]);
        acc2[0][2] = ffma2(aA.x, bp2, acc2[0][2]);
        acc2[0][3] = ffma2(aA.x, bp3, acc2[0][3]);
        acc2[1][0] = ffma2(aA.y, bp0, acc2[1][0]);
        acc2[1][1] = ffma2(aA.y, bp1, acc2[1][1]);
        acc2[1][2] = ffma2(aA.y, bp2, acc2[1][2]);
        acc2[1][3] = ffma2(aA.y, bp3, acc2[1][3]);
        acc2[2][0] = ffma2(aB.x, bp0, acc2[2][0]);
        acc2[2][1] = ffma2(aB.x, bp1, acc2[2][1]);
        acc2[2][2] = ffma2(aB.x, bp2, acc2[2][2]);
        acc2[2][3] = ffma2(aB.x, bp3, acc2[2][3]);
        acc2[3][0] = ffma2(aB.y, bp0, acc2[3][0]);
        acc2[3][1] = ffma2(aB.y, bp1, acc2[3][1]);
        acc2[3][2] = ffma2(aB.y, bp2, acc2[3][2]);
        acc2[3][3] = ffma2(aB.y, bp3, acc2[3][3]);
    }
    __syncthreads();   // all reads of Zs done before reuse as S0s
    #pragma unroll
    for (int p = 0; p < 4; p++)
        #pragma unroll
        for (int j = 0; j < 4; j++) {
            float lo, hi;
            unpack2(acc2[p][j], lo, hi);
            Zs[(ty * 8 + 2 * p) * 64 + tx * 4 + j] = lo;
            Zs[(ty * 8 + 2 * p + 1) * 64 + tx * 4 + j] = hi;
        }
    __syncthreads();
    float w = wsh;
    #pragma unroll
    for (int rr = 0; rr < 8; rr++) {
        int mr = ty * 8 + rr;
        int t = tgs[mr];
        int trow = (t < 64) ? t : 63;
        float corr = (t < 64) ? (w * Zs[mr * 64 + trow]) : 0.0f;
        float4 s0v = *(const float4*)&Zs[mr * 64 + tx * 4];
        float4 cv  = *(const float4*)&Cs[trow * 68 + tx * 4];
        float4 o;
        o.x = w * s0v.x - cv.x * corr;
        o.y = w * s0v.y - cv.y * corr;
        o.z = w * s0v.z - cv.z * corr;
        o.w = w * s0v.w - cv.w * corr;
        int n0 = tx * 4;
        if (t == n0 + 0) o.x = 0.0f;
        if (t == n0 + 1) o.y = 0.0f;
        if (t == n0 + 2) o.z = 0.0f;
        if (t == n0 + 3) o.w = 0.0f;
        *(float4*)&out[SOFF + ((size_t)b * 512 + i0 + mr) * 64 + n0] = o;
    }
}

// ---------------- launch ----------------
extern "C" void kernel_launch(void* const* d_in, const int* in_sizes, int n_in,
                              void* d_out, int out_size) {
    const float* Lp  = (const float*)d_in[0];
    const float* eps = (const float*)d_in[1];
    const float* gum = (const float*)d_in[2];
    const float* z   = (const float*)d_in[3];
    const float* W1  = (const float*)d_in[4];
    const float* b1  = (const float*)d_in[5];
    const float* W2  = (const float*)d_in[6];
    const float* b2  = (const float*)d_in[7];
    const float* W3  = (const float*)d_in[8];
    const float* b3  = (const float*)d_in[9];
    const int*   tg  = (const int*)d_in[10];
    float* out = (float*)d_out;

    cudaFuncSetAttribute(k_sinkgreedy, cudaFuncAttributeMaxDynamicSharedMemorySize, 50176);
    cudaFuncSetAttribute(k_samples, cudaFuncAttributeMaxDynamicSharedMemorySize, 50176);

    k_prep<<<512, 256>>>(Lp, eps, out);

    sgemm<<<dim3(8, 4, 16), 256>>>(0, W1, 512, 2017, 128);
    k_epi_gelu<<<1024, 256>>>(0, b1);

    sgemm<<<dim3(8, 4, 16), 256>>>(1, W2, 512, 512, 32);
    k_epi_gelu<<<1024, 256>>>(1, b2);

    sgemm<<<dim3(64, 4, 2), 256>>>(2, W3, 4096, 512, 256);

    k_sinkgreedy<<<512, 256, 49920>>>(b3, gum, out);
    k_samples<<<2048, 256, 50176>>>(z, tg, out);
}